// round 2
// baseline (speedup 1.0000x reference)
#include <cuda_runtime.h>

#define N_EDGES   400000
#define TE        64
#define NBLK      (N_EDGES / TE)   // 6250, exact
#define WN        576              // WEIGHT_NUMEL
#define C3F       0.5773502691896257f
// S0 = sqrt(1/24) * (1/8 wvec scale) * (1/4 output scale) = sqrt(1/24)/32
#define S0F       0.006378879538497861f
#define SILU_NORM 1.6791767923989418f

// Permuted copy of W2 (64 x 576), column order matched to per-thread slices.
__device__ float g_W2p[64 * WN];

__global__ void zero_kernel(float* __restrict__ out, int n) {
  int i = blockIdx.x * blockDim.x + threadIdx.x;
  if (i < n) out[i] = 0.0f;
}

// mprime = (g*4 + r)*16 + j  ->  original column m of W2.
// g 0..3 : w1 slice, w = r + 4g, u = j          (out0)
// g 4..5 : w4 slice, w = r + 4*(2(g-4)+j/8), u=j%8 (out0, *INV_SQRT3)
// g 6..7 : w2 slice, w = 2r + (g-6), u = j      (out1 part A)
// g 8    : w3 slice, w = 2r + j/8, u = j%8      (out1 part B)
__global__ void permute_w2(const float* __restrict__ W2) {
  int mp = blockIdx.x * blockDim.x + threadIdx.x;
  if (mp >= WN) return;
  int j = mp & 15, gr = mp >> 4, g = gr >> 2, r = gr & 3;
  int m;
  if (g < 4)       m = j * 16 + r + 4 * g;
  else if (g < 6)  m = 448 + (j & 7) * 16 + r + 4 * ((g - 4) * 2 + (j >> 3));
  else if (g < 8)  m = 256 + j * 8 + 2 * r + (g - 6);
  else             m = 384 + (j & 7) * 8 + 2 * r + (j >> 3);
  for (int k = 0; k < 64; k++)
    g_W2p[k * WN + mp] = W2[k * WN + m];
}

template <int G>
__device__ __forceinline__ void do_chunk(
    int t, int e, int r,
    const float* __restrict__ sH, float* __restrict__ sW,
    const float* __restrict__ sX,
    float y0_, float y1x, float y1y, float y1z,
    const float (&z4)[8], float (&acc0)[4], float (&a1)[6])
{
  __syncthreads();  // previous chunk's consumers done before overwrite
  #pragma unroll 4
  for (int i4 = t; i4 < 1024; i4 += 256) {
    int kk = i4 >> 4, cc = i4 & 15;
    ((float4*)sW)[i4] = *(const float4*)(g_W2p + kk * WN + G * 64 + cc * 4);
  }
  __syncthreads();

  float wv[16];
  #pragma unroll
  for (int j = 0; j < 16; j++) wv[j] = 0.0f;

  #pragma unroll 4
  for (int k = 0; k < 64; k++) {
    float hk = sH[k * 65 + e];
    const float4* wp = (const float4*)(sW + k * 64 + r * 16);
    float4 a = wp[0], b = wp[1], c = wp[2], d = wp[3];
    wv[0]  += hk * a.x;  wv[1]  += hk * a.y;  wv[2]  += hk * a.z;  wv[3]  += hk * a.w;
    wv[4]  += hk * b.x;  wv[5]  += hk * b.y;  wv[6]  += hk * b.z;  wv[7]  += hk * b.w;
    wv[8]  += hk * c.x;  wv[9]  += hk * c.y;  wv[10] += hk * c.z;  wv[11] += hk * c.w;
    wv[12] += hk * d.x;  wv[13] += hk * d.y;  wv[14] += hk * d.z;  wv[15] += hk * d.w;
  }

  if (G < 4) {                       // w1: out0[w=r+4G] += y0 * sum_u x0[u]*wv[u]
    float s = 0.0f;
    #pragma unroll
    for (int j = 0; j < 16; j++) s += sX[e * 41 + j] * wv[j];
    acc0[G < 4 ? G : 0] += y0_ * s;
  } else if (G < 6) {                // w4: out0 += C3 * sum_u z4[u]*wv
    float sA = 0.0f, sB = 0.0f;
    #pragma unroll
    for (int u = 0; u < 8; u++) { sA += z4[u] * wv[u]; sB += z4[u] * wv[8 + u]; }
    acc0[2 * (G - 4) + 0] += C3F * sA;
    acc0[2 * (G - 4) + 1] += C3F * sB;
  } else if (G < 8) {                // w2: q = sum_u x0[u]*wv; out1[w][i] += q*y1[i]
    float q = 0.0f;
    #pragma unroll
    for (int j = 0; j < 16; j++) q += sX[e * 41 + j] * wv[j];
    int b = 3 * (G - 6);
    a1[b + 0] += q * y1x;  a1[b + 1] += q * y1y;  a1[b + 2] += q * y1z;
  } else {                           // w3: out1[w][i] += y0 * sum_u x1[u][i]*wv
    float s0 = 0, s1 = 0, s2 = 0, t0 = 0, t1 = 0, t2 = 0;
    #pragma unroll
    for (int u = 0; u < 8; u++) {
      float x0v = sX[e * 41 + 16 + 3 * u + 0];
      float x1v = sX[e * 41 + 16 + 3 * u + 1];
      float x2v = sX[e * 41 + 16 + 3 * u + 2];
      s0 += x0v * wv[u];     s1 += x1v * wv[u];     s2 += x2v * wv[u];
      t0 += x0v * wv[8 + u]; t1 += x1v * wv[8 + u]; t2 += x2v * wv[8 + u];
    }
    a1[0] += y0_ * s0; a1[1] += y0_ * s1; a1[2] += y0_ * s2;
    a1[3] += y0_ * t0; a1[4] += y0_ * t1; a1[5] += y0_ * t2;
  }
}

__global__ __launch_bounds__(256, 2) void fused_conv(
    const float* __restrict__ node_input,
    const int*   __restrict__ edge_src,
    const int*   __restrict__ edge_dst,
    const float* __restrict__ edge_attr,
    const float* __restrict__ dist,
    const float* __restrict__ W1,
    float* __restrict__ out)
{
  __shared__ float sH[64 * 65];   // dist tile transposed [k][e]; later h [k][e]
  __shared__ float sW[64 * 64];   // W1; later W2 chunks
  __shared__ float sX[64 * 41];   // gathered node features
  __shared__ float sY[64 * 5];    // edge_attr
  __shared__ int   sSrc[64];
  __shared__ int   sDst[64];

  const int t = threadIdx.x;
  const int e = t & 63;
  const int r = t >> 6;
  const long e0 = (long)blockIdx.x * TE;

  if (t < 64)        sDst[t]       = edge_dst[e0 + t];
  else if (t < 128)  sSrc[t - 64]  = edge_src[e0 + t - 64];

  // dist tile, transposed store (conflict-free reads later)
  for (int idx = t; idx < 64 * 64; idx += 256) {
    int er = idx >> 6, k = idx & 63;
    sH[k * 65 + er] = dist[(e0 + er) * 64 + k];
  }
  // W1 straight copy (broadcast-read later)
  {
    const float4* W14 = (const float4*)W1;
    float4* sW4 = (float4*)sW;
    #pragma unroll 4
    for (int i4 = t; i4 < 1024; i4 += 256) sW4[i4] = W14[i4];
  }
  // edge_attr (stride 5 to kill bank conflicts)
  {
    int er = t >> 2, c = t & 3;
    sY[er * 5 + c] = edge_attr[(e0 + er) * 4 + c];
  }
  __syncthreads();

  // gather x = node_input[edge_dst] (L2-resident table)
  for (int idx = t; idx < 64 * 40; idx += 256) {
    int er = idx / 40, c = idx - er * 40;
    sX[er * 41 + c] = node_input[(long)sDst[er] * 40 + c];
  }

  // ---- GEMM1: h[e][r*16+j] = SILU_NORM * silu( (d @ W1)/8 ) ----
  float acc[16];
  #pragma unroll
  for (int j = 0; j < 16; j++) acc[j] = 0.0f;
  #pragma unroll 4
  for (int k = 0; k < 64; k++) {
    float dk = sH[k * 65 + e];
    const float4* wp = (const float4*)(sW + k * 64 + r * 16);
    float4 a = wp[0], b = wp[1], c = wp[2], d = wp[3];
    acc[0]  += dk * a.x;  acc[1]  += dk * a.y;  acc[2]  += dk * a.z;  acc[3]  += dk * a.w;
    acc[4]  += dk * b.x;  acc[5]  += dk * b.y;  acc[6]  += dk * b.z;  acc[7]  += dk * b.w;
    acc[8]  += dk * c.x;  acc[9]  += dk * c.y;  acc[10] += dk * c.z;  acc[11] += dk * c.w;
    acc[12] += dk * d.x;  acc[13] += dk * d.y;  acc[14] += dk * d.z;  acc[15] += dk * d.w;
  }
  __syncthreads();  // all reads of sH (dist) and sW (W1) complete

  #pragma unroll
  for (int j = 0; j < 16; j++) {
    float v = acc[j] * 0.125f;
    float sg = 1.0f / (1.0f + __expf(-v));
    sH[(r * 16 + j) * 65 + e] = SILU_NORM * v * sg;   // h transposed [k][e]
  }

  // per-edge scalars
  float y0_ = sY[e * 5 + 0];
  float y1x = sY[e * 5 + 1], y1y = sY[e * 5 + 2], y1z = sY[e * 5 + 3];
  float z4[8];
  #pragma unroll
  for (int u = 0; u < 8; u++) {
    z4[u] = sX[e * 41 + 16 + 3 * u + 0] * y1x
          + sX[e * 41 + 16 + 3 * u + 1] * y1y
          + sX[e * 41 + 16 + 3 * u + 2] * y1z;
  }

  float acc0[4] = {0, 0, 0, 0};
  float a1[6]   = {0, 0, 0, 0, 0, 0};

  // ---- GEMM2 + tensor product, 9 chunks of 64 permuted W2 columns ----
  do_chunk<0>(t, e, r, sH, sW, sX, y0_, y1x, y1y, y1z, z4, acc0, a1);
  do_chunk<1>(t, e, r, sH, sW, sX, y0_, y1x, y1y, y1z, z4, acc0, a1);
  do_chunk<2>(t, e, r, sH, sW, sX, y0_, y1x, y1y, y1z, z4, acc0, a1);
  do_chunk<3>(t, e, r, sH, sW, sX, y0_, y1x, y1y, y1z, z4, acc0, a1);
  do_chunk<4>(t, e, r, sH, sW, sX, y0_, y1x, y1y, y1z, z4, acc0, a1);
  do_chunk<5>(t, e, r, sH, sW, sX, y0_, y1x, y1y, y1z, z4, acc0, a1);
  do_chunk<6>(t, e, r, sH, sW, sX, y0_, y1x, y1y, y1z, z4, acc0, a1);
  do_chunk<7>(t, e, r, sH, sW, sX, y0_, y1x, y1y, y1z, z4, acc0, a1);
  do_chunk<8>(t, e, r, sH, sW, sX, y0_, y1x, y1y, y1z, z4, acc0, a1);

  // ---- scatter (disjoint columns across the 4 threads of an edge) ----
  int base = sSrc[e] * 40;
  #pragma unroll
  for (int gi = 0; gi < 4; gi++)
    atomicAdd(out + base + r + 4 * gi, S0F * acc0[gi]);
  #pragma unroll
  for (int wp = 0; wp < 2; wp++)
    #pragma unroll
    for (int i = 0; i < 3; i++)
      atomicAdd(out + base + 16 + (2 * r + wp) * 3 + i, S0F * a1[wp * 3 + i]);
}

extern "C" void kernel_launch(void* const* d_in, const int* in_sizes, int n_in,
                              void* d_out, int out_size) {
  const float* node_input = (const float*)d_in[0];
  const int*   edge_src   = (const int*)d_in[1];
  const int*   edge_dst   = (const int*)d_in[2];
  const float* edge_attr  = (const float*)d_in[3];
  const float* dist       = (const float*)d_in[4];
  const float* W1         = (const float*)d_in[5];
  const float* W2         = (const float*)d_in[6];
  float* out = (float*)d_out;

  zero_kernel<<<(out_size + 511) / 512, 512>>>(out, out_size);
  permute_w2<<<(WN + 127) / 128, 128>>>(W2);
  fused_conv<<<NBLK, 256>>>(node_input, edge_src, edge_dst, edge_attr, dist, W1, out);
}

// round 3
// speedup vs baseline: 1.0635x; 1.0635x over previous
#include <cuda_runtime.h>

#define N_EDGES   400000
#define TE        64
#define NBLK      (N_EDGES / TE)   // 6250, exact
#define WN        576              // WEIGHT_NUMEL
#define C3F       0.5773502691896257f
// S0 = sqrt(1/24) * (1/8 wvec scale) * (1/4 output scale) = sqrt(1/24)/32
#define S0F       0.006378879538497861f
#define SILU_NORM 1.6791767923989418f

typedef unsigned long long u64;

__device__ __forceinline__ void ffma2(u64 &d, u64 a, u64 b) {
  asm("fma.rn.f32x2 %0, %1, %2, %0;" : "+l"(d) : "l"(a), "l"(b));
}
__device__ __forceinline__ u64 dup2(float x) {
  u64 r; asm("mov.b64 %0, {%1, %1};" : "=l"(r) : "f"(x)); return r;
}
__device__ __forceinline__ void unpack2(u64 v, float &lo, float &hi) {
  asm("mov.b64 {%0, %1}, %2;" : "=f"(lo), "=f"(hi) : "l"(v));
}

// Permuted copy of W2 (64 x 576), column order matched to per-thread slices.
__device__ float g_W2p[64 * WN];

// mprime = (g*4 + r)*16 + j  ->  original column m of W2.
// g 0..3 : w1 slice, w = r + 4g, u = j            (out0)
// g 4..5 : w4 slice, w = r + 4*(2(g-4)+j/8), u=j%8 (out0, *INV_SQRT3)
// g 6..7 : w2 slice, w = 2r + (g-6), u = j        (out1 part A)
// g 8    : w3 slice, w = 2r + j/8, u = j%8        (out1 part B)
__global__ void permute_w2(const float* __restrict__ W2) {
  int mp = blockIdx.x * blockDim.x + threadIdx.x;
  if (mp >= WN) return;
  int j = mp & 15, gr = mp >> 4, g = gr >> 2, r = gr & 3;
  int m;
  if (g < 4)       m = j * 16 + r + 4 * g;
  else if (g < 6)  m = 448 + (j & 7) * 16 + r + 4 * ((g - 4) * 2 + (j >> 3));
  else if (g < 8)  m = 256 + j * 8 + 2 * r + (g - 6);
  else             m = 384 + (j & 7) * 8 + 2 * r + (j >> 3);
  for (int k = 0; k < 64; k++)
    g_W2p[k * WN + mp] = W2[k * WN + m];
}

template <int G>
__device__ __forceinline__ void do_chunk(
    int t, int e, int r,
    const float* __restrict__ sH, float* __restrict__ sW,
    const float* __restrict__ sX,
    float y0_, float y1x, float y1y, float y1z,
    const float (&z4)[8], float (&acc0)[4], float (&a1)[6])
{
  __syncthreads();  // previous chunk's consumers done before overwrite
  #pragma unroll 4
  for (int i4 = t; i4 < 1024; i4 += 256) {
    int kk = i4 >> 4, cc = i4 & 15;
    ((float4*)sW)[i4] = *(const float4*)(g_W2p + kk * WN + G * 64 + cc * 4);
  }
  __syncthreads();

  u64 wv2[8];
  #pragma unroll
  for (int j = 0; j < 8; j++) wv2[j] = 0ull;

  #pragma unroll 4
  for (int k = 0; k < 64; k++) {
    u64 hk2 = dup2(sH[k * 65 + e]);
    const ulonglong2* wp = (const ulonglong2*)(sW + k * 64 + r * 16);
    ulonglong2 p0 = wp[0], p1 = wp[1], p2 = wp[2], p3 = wp[3];
    ffma2(wv2[0], hk2, p0.x);  ffma2(wv2[1], hk2, p0.y);
    ffma2(wv2[2], hk2, p1.x);  ffma2(wv2[3], hk2, p1.y);
    ffma2(wv2[4], hk2, p2.x);  ffma2(wv2[5], hk2, p2.y);
    ffma2(wv2[6], hk2, p3.x);  ffma2(wv2[7], hk2, p3.y);
  }

  float wv[16];
  #pragma unroll
  for (int j = 0; j < 8; j++) unpack2(wv2[j], wv[2 * j], wv[2 * j + 1]);

  if (G < 4) {                       // w1: out0[w=r+4G] += y0 * sum_u x0[u]*wv[u]
    float s = 0.0f;
    #pragma unroll
    for (int j = 0; j < 16; j++) s += sX[e * 41 + j] * wv[j];
    acc0[G < 4 ? G : 0] += y0_ * s;
  } else if (G < 6) {                // w4: out0 += C3 * sum_u z4[u]*wv
    float sA = 0.0f, sB = 0.0f;
    #pragma unroll
    for (int u = 0; u < 8; u++) { sA += z4[u] * wv[u]; sB += z4[u] * wv[8 + u]; }
    acc0[2 * (G - 4) + 0] += C3F * sA;
    acc0[2 * (G - 4) + 1] += C3F * sB;
  } else if (G < 8) {                // w2: q = sum_u x0[u]*wv; out1[w][i] += q*y1[i]
    float q = 0.0f;
    #pragma unroll
    for (int j = 0; j < 16; j++) q += sX[e * 41 + j] * wv[j];
    int b = 3 * (G - 6);
    a1[b + 0] += q * y1x;  a1[b + 1] += q * y1y;  a1[b + 2] += q * y1z;
  } else {                           // w3: out1[w][i] += y0 * sum_u x1[u][i]*wv
    float s0 = 0, s1 = 0, s2 = 0, t0 = 0, t1 = 0, t2 = 0;
    #pragma unroll
    for (int u = 0; u < 8; u++) {
      float x0v = sX[e * 41 + 16 + 3 * u + 0];
      float x1v = sX[e * 41 + 16 + 3 * u + 1];
      float x2v = sX[e * 41 + 16 + 3 * u + 2];
      s0 += x0v * wv[u];     s1 += x1v * wv[u];     s2 += x2v * wv[u];
      t0 += x0v * wv[8 + u]; t1 += x1v * wv[8 + u]; t2 += x2v * wv[8 + u];
    }
    a1[0] += y0_ * s0; a1[1] += y0_ * s1; a1[2] += y0_ * s2;
    a1[3] += y0_ * t0; a1[4] += y0_ * t1; a1[5] += y0_ * t2;
  }
}

__global__ __launch_bounds__(256, 2) void fused_conv(
    const float* __restrict__ node_input,
    const int*   __restrict__ edge_src,
    const int*   __restrict__ edge_dst,
    const float* __restrict__ edge_attr,
    const float* __restrict__ dist,
    const float* __restrict__ W1,
    float* __restrict__ out)
{
  __shared__ float sH[64 * 65];   // dist tile transposed [k][e]; later h [k][e]
  __shared__ float sW[64 * 64];   // W1; later W2 chunks
  __shared__ float sX[64 * 41];   // gathered node features
  __shared__ float sY[64 * 5];    // edge_attr
  __shared__ int   sSrc[64];
  __shared__ int   sDst[64];

  const int t = threadIdx.x;
  const int e = t & 63;
  const int r = t >> 6;
  const long e0 = (long)blockIdx.x * TE;

  if (t < 64)        sDst[t]       = edge_dst[e0 + t];
  else if (t < 128)  sSrc[t - 64]  = edge_src[e0 + t - 64];

  // dist tile, transposed store (conflict-free reads later)
  for (int idx = t; idx < 64 * 64; idx += 256) {
    int er = idx >> 6, k = idx & 63;
    sH[k * 65 + er] = dist[(e0 + er) * 64 + k];
  }
  // W1 straight copy (broadcast-read later)
  {
    const float4* W14 = (const float4*)W1;
    float4* sW4 = (float4*)sW;
    #pragma unroll 4
    for (int i4 = t; i4 < 1024; i4 += 256) sW4[i4] = W14[i4];
  }
  // edge_attr (stride 5 to kill bank conflicts)
  {
    int er = t >> 2, c = t & 3;
    sY[er * 5 + c] = edge_attr[(e0 + er) * 4 + c];
  }
  __syncthreads();

  // gather x = node_input[edge_dst] (L2-resident table)
  for (int idx = t; idx < 64 * 40; idx += 256) {
    int er = idx / 40, c = idx - er * 40;
    sX[er * 41 + c] = node_input[(long)sDst[er] * 40 + c];
  }

  // ---- GEMM1: h[e][r*16+j] = SILU_NORM * silu( (d @ W1)/8 ) ----
  u64 acc2[8];
  #pragma unroll
  for (int j = 0; j < 8; j++) acc2[j] = 0ull;
  #pragma unroll 4
  for (int k = 0; k < 64; k++) {
    u64 dk2 = dup2(sH[k * 65 + e]);
    const ulonglong2* wp = (const ulonglong2*)(sW + k * 64 + r * 16);
    ulonglong2 p0 = wp[0], p1 = wp[1], p2 = wp[2], p3 = wp[3];
    ffma2(acc2[0], dk2, p0.x);  ffma2(acc2[1], dk2, p0.y);
    ffma2(acc2[2], dk2, p1.x);  ffma2(acc2[3], dk2, p1.y);
    ffma2(acc2[4], dk2, p2.x);  ffma2(acc2[5], dk2, p2.y);
    ffma2(acc2[6], dk2, p3.x);  ffma2(acc2[7], dk2, p3.y);
  }
  __syncthreads();  // all reads of sH (dist) and sW (W1) complete

  #pragma unroll
  for (int j = 0; j < 8; j++) {
    float v0, v1;
    unpack2(acc2[j], v0, v1);
    v0 *= 0.125f;  v1 *= 0.125f;
    float sg0 = 1.0f / (1.0f + __expf(-v0));
    float sg1 = 1.0f / (1.0f + __expf(-v1));
    sH[(r * 16 + 2 * j + 0) * 65 + e] = SILU_NORM * v0 * sg0;
    sH[(r * 16 + 2 * j + 1) * 65 + e] = SILU_NORM * v1 * sg1;
  }

  // per-edge scalars
  float y0_ = sY[e * 5 + 0];
  float y1x = sY[e * 5 + 1], y1y = sY[e * 5 + 2], y1z = sY[e * 5 + 3];
  float z4[8];
  #pragma unroll
  for (int u = 0; u < 8; u++) {
    z4[u] = sX[e * 41 + 16 + 3 * u + 0] * y1x
          + sX[e * 41 + 16 + 3 * u + 1] * y1y
          + sX[e * 41 + 16 + 3 * u + 2] * y1z;
  }

  float acc0[4] = {0, 0, 0, 0};
  float a1[6]   = {0, 0, 0, 0, 0, 0};

  // ---- GEMM2 + tensor product, 9 chunks of 64 permuted W2 columns ----
  do_chunk<0>(t, e, r, sH, sW, sX, y0_, y1x, y1y, y1z, z4, acc0, a1);
  do_chunk<1>(t, e, r, sH, sW, sX, y0_, y1x, y1y, y1z, z4, acc0, a1);
  do_chunk<2>(t, e, r, sH, sW, sX, y0_, y1x, y1y, y1z, z4, acc0, a1);
  do_chunk<3>(t, e, r, sH, sW, sX, y0_, y1x, y1y, y1z, z4, acc0, a1);
  do_chunk<4>(t, e, r, sH, sW, sX, y0_, y1x, y1y, y1z, z4, acc0, a1);
  do_chunk<5>(t, e, r, sH, sW, sX, y0_, y1x, y1y, y1z, z4, acc0, a1);
  do_chunk<6>(t, e, r, sH, sW, sX, y0_, y1x, y1y, y1z, z4, acc0, a1);
  do_chunk<7>(t, e, r, sH, sW, sX, y0_, y1x, y1y, y1z, z4, acc0, a1);
  do_chunk<8>(t, e, r, sH, sW, sX, y0_, y1x, y1y, y1z, z4, acc0, a1);

  // ---- scatter (disjoint columns across the 4 threads of an edge) ----
  int base = sSrc[e] * 40;
  #pragma unroll
  for (int gi = 0; gi < 4; gi++)
    atomicAdd(out + base + r + 4 * gi, S0F * acc0[gi]);
  #pragma unroll
  for (int wp = 0; wp < 2; wp++)
    #pragma unroll
    for (int i = 0; i < 3; i++)
      atomicAdd(out + base + 16 + (2 * r + wp) * 3 + i, S0F * a1[wp * 3 + i]);
}

extern "C" void kernel_launch(void* const* d_in, const int* in_sizes, int n_in,
                              void* d_out, int out_size) {
  const float* node_input = (const float*)d_in[0];
  const int*   edge_src   = (const int*)d_in[1];
  const int*   edge_dst   = (const int*)d_in[2];
  const float* edge_attr  = (const float*)d_in[3];
  const float* dist       = (const float*)d_in[4];
  const float* W1         = (const float*)d_in[5];
  const float* W2         = (const float*)d_in[6];
  float* out = (float*)d_out;

  cudaMemsetAsync(out, 0, (size_t)out_size * sizeof(float));
  permute_w2<<<(WN + 127) / 128, 128>>>(W2);
  fused_conv<<<NBLK, 256>>>(node_input, edge_src, edge_dst, edge_attr, dist, W1, out);
}

// round 4
// speedup vs baseline: 1.5247x; 1.4337x over previous
#include <cuda_runtime.h>

#define N_EDGES   400000
#define TE        128
#define NBLK      (N_EDGES / TE)   // 3125, exact
#define WN        576              // WEIGHT_NUMEL
#define SHS       129              // sH row stride (odd: conflict-free both phases)
#define C3F       0.5773502691896257f
// S0 = sqrt(1/24) * (1/8 wvec scale) * (1/4 output scale) = sqrt(1/24)/32
#define S0F       0.006378879538497861f
#define SILU_NORM 1.6791767923989418f

typedef unsigned long long u64;

__device__ __forceinline__ void ffma2(u64 &d, u64 a, u64 b) {
  asm("fma.rn.f32x2 %0, %1, %2, %0;" : "+l"(d) : "l"(a), "l"(b));
}
__device__ __forceinline__ u64 dup2(float x) {
  u64 r; asm("mov.b64 %0, {%1, %1};" : "=l"(r) : "f"(x)); return r;
}
__device__ __forceinline__ void unpack2(u64 v, float &lo, float &hi) {
  asm("mov.b64 {%0, %1}, %2;" : "=f"(lo), "=f"(hi) : "l"(v));
}

// Shared layout (floats):
//   sH : 64*SHS        (dist tile transposed [k][e]; later h [k][e])
//   sW : 64*64         (W1; later W2 chunks)
//   sX : 128*41        (gathered node features)
//   sY : 128*5         (edge_attr)
//   sSrc/sDst : 128 ints each
#define OFF_H   0
#define OFF_W   (64 * SHS)
#define OFF_X   (OFF_W + 64 * 64)
#define OFF_Y   (OFF_X + 128 * 41)
#define OFF_SRC (OFF_Y + 128 * 5)
#define OFF_DST (OFF_SRC + 128)
#define SMEM_FLOATS (OFF_DST + 128)
#define SMEM_BYTES  (SMEM_FLOATS * 4)

// Permuted copy of W2 (64 x 576), column order matched to per-thread slices.
__device__ float g_W2p[64 * WN];

// mprime = (g*4 + r)*16 + j  ->  original column m of W2.
// g 0..3 : w1 slice, w = r + 4g, u = j            (out0)
// g 4..5 : w4 slice, w = r + 4*(2(g-4)+j/8), u=j%8 (out0, *INV_SQRT3)
// g 6..7 : w2 slice, w = 2r + (g-6), u = j        (out1 part A)
// g 8    : w3 slice, w = 2r + j/8, u = j%8        (out1 part B)
__global__ void permute_w2(const float* __restrict__ W2) {
  int mp = blockIdx.x * blockDim.x + threadIdx.x;
  if (mp >= WN) return;
  int j = mp & 15, gr = mp >> 4, g = gr >> 2, r = gr & 3;
  int m;
  if (g < 4)       m = j * 16 + r + 4 * g;
  else if (g < 6)  m = 448 + (j & 7) * 16 + r + 4 * ((g - 4) * 2 + (j >> 3));
  else if (g < 8)  m = 256 + j * 8 + 2 * r + (g - 6);
  else             m = 384 + (j & 7) * 8 + 2 * r + (j >> 3);
  for (int k = 0; k < 64; k++)
    g_W2p[k * WN + mp] = W2[k * WN + m];
}

template <int G>
__device__ __forceinline__ void do_chunk(
    int t, int e, int r,
    float* __restrict__ sm,
    const float y0_[2], const float y1x_[2], const float y1y_[2], const float y1z_[2],
    float (&acc0)[2][4], float (&a1)[2][6])
{
  const float* sH = sm + OFF_H;
  float*       sW = sm + OFF_W;
  const float* sX = sm + OFF_X;

  __syncthreads();  // previous chunk's consumers done before overwrite
  #pragma unroll 4
  for (int i4 = t; i4 < 1024; i4 += 256) {
    int kk = i4 >> 4, cc = i4 & 15;
    ((float4*)sW)[i4] = *(const float4*)(g_W2p + kk * WN + G * 64 + cc * 4);
  }
  __syncthreads();

  u64 wvA[8], wvB[8];
  #pragma unroll
  for (int j = 0; j < 8; j++) { wvA[j] = 0ull; wvB[j] = 0ull; }

  #pragma unroll 2
  for (int k = 0; k < 64; k++) {
    u64 h0 = dup2(sH[k * SHS + e]);
    u64 h1 = dup2(sH[k * SHS + e + 64]);
    const ulonglong2* wp = (const ulonglong2*)(sW + k * 64 + r * 16);
    ulonglong2 p0 = wp[0], p1 = wp[1], p2 = wp[2], p3 = wp[3];
    ffma2(wvA[0], h0, p0.x);  ffma2(wvA[1], h0, p0.y);
    ffma2(wvA[2], h0, p1.x);  ffma2(wvA[3], h0, p1.y);
    ffma2(wvA[4], h0, p2.x);  ffma2(wvA[5], h0, p2.y);
    ffma2(wvA[6], h0, p3.x);  ffma2(wvA[7], h0, p3.y);
    ffma2(wvB[0], h1, p0.x);  ffma2(wvB[1], h1, p0.y);
    ffma2(wvB[2], h1, p1.x);  ffma2(wvB[3], h1, p1.y);
    ffma2(wvB[4], h1, p2.x);  ffma2(wvB[5], h1, p2.y);
    ffma2(wvB[6], h1, p3.x);  ffma2(wvB[7], h1, p3.y);
  }

  #pragma unroll
  for (int ee = 0; ee < 2; ee++) {
    const int eidx = e + 64 * ee;
    float wv[16];
    #pragma unroll
    for (int j = 0; j < 8; j++)
      unpack2(ee ? wvB[j] : wvA[j], wv[2 * j], wv[2 * j + 1]);

    if (G < 4) {                 // w1: out0[w=r+4G] += y0 * sum_u x0[u]*wv[u]
      float s = 0.0f;
      #pragma unroll
      for (int j = 0; j < 16; j++) s += sX[eidx * 41 + j] * wv[j];
      acc0[ee][G < 4 ? G : 0] += y0_[ee] * s;
    } else if (G < 6) {          // w4: out0 += C3 * sum_u z4[u]*wv  (z4 recomputed)
      float sA = 0.0f, sB = 0.0f;
      #pragma unroll
      for (int u = 0; u < 8; u++) {
        float z = sX[eidx * 41 + 16 + 3 * u + 0] * y1x_[ee]
                + sX[eidx * 41 + 16 + 3 * u + 1] * y1y_[ee]
                + sX[eidx * 41 + 16 + 3 * u + 2] * y1z_[ee];
        sA += z * wv[u];  sB += z * wv[8 + u];
      }
      acc0[ee][2 * (G - 4) + 0] += C3F * sA;
      acc0[ee][2 * (G - 4) + 1] += C3F * sB;
    } else if (G < 8) {          // w2: q = sum_u x0[u]*wv; out1[w][i] += q*y1[i]
      float q = 0.0f;
      #pragma unroll
      for (int j = 0; j < 16; j++) q += sX[eidx * 41 + j] * wv[j];
      int b = 3 * (G - 6);
      a1[ee][b + 0] += q * y1x_[ee];
      a1[ee][b + 1] += q * y1y_[ee];
      a1[ee][b + 2] += q * y1z_[ee];
    } else {                     // w3: out1[w][i] += y0 * sum_u x1[u][i]*wv
      float s0 = 0, s1 = 0, s2 = 0, t0 = 0, t1 = 0, t2 = 0;
      #pragma unroll
      for (int u = 0; u < 8; u++) {
        float x0v = sX[eidx * 41 + 16 + 3 * u + 0];
        float x1v = sX[eidx * 41 + 16 + 3 * u + 1];
        float x2v = sX[eidx * 41 + 16 + 3 * u + 2];
        s0 += x0v * wv[u];     s1 += x1v * wv[u];     s2 += x2v * wv[u];
        t0 += x0v * wv[8 + u]; t1 += x1v * wv[8 + u]; t2 += x2v * wv[8 + u];
      }
      a1[ee][0] += y0_[ee] * s0; a1[ee][1] += y0_[ee] * s1; a1[ee][2] += y0_[ee] * s2;
      a1[ee][3] += y0_[ee] * t0; a1[ee][4] += y0_[ee] * t1; a1[ee][5] += y0_[ee] * t2;
    }
  }
}

__global__ __launch_bounds__(256, 2) void fused_conv(
    const float* __restrict__ node_input,
    const int*   __restrict__ edge_src,
    const int*   __restrict__ edge_dst,
    const float* __restrict__ edge_attr,
    const float* __restrict__ dist,
    const float* __restrict__ W1,
    float* __restrict__ out)
{
  extern __shared__ float sm[];
  float* sH = sm + OFF_H;
  float* sW = sm + OFF_W;
  float* sX = sm + OFF_X;
  float* sY = sm + OFF_Y;
  int*   sSrc = (int*)(sm + OFF_SRC);
  int*   sDst = (int*)(sm + OFF_DST);

  const int t = threadIdx.x;
  const int e = t & 63;
  const int r = t >> 6;
  const long e0 = (long)blockIdx.x * TE;

  if (t < 128) sDst[t]        = edge_dst[e0 + t];
  else         sSrc[t - 128]  = edge_src[e0 + t - 128];

  // dist tile, transposed store (stride SHS odd -> conflict-free)
  for (int idx = t; idx < 128 * 64; idx += 256) {
    int er = idx >> 6, k = idx & 63;
    sH[k * SHS + er] = dist[(e0 + er) * 64 + k];
  }
  // W1 straight copy (broadcast-read later)
  {
    const float4* W14 = (const float4*)W1;
    float4* sW4 = (float4*)sW;
    #pragma unroll 4
    for (int i4 = t; i4 < 1024; i4 += 256) sW4[i4] = W14[i4];
  }
  // edge_attr (stride 5 kills bank conflicts)
  for (int idx = t; idx < 128 * 4; idx += 256) {
    int er = idx >> 2, c = idx & 3;
    sY[er * 5 + c] = edge_attr[(e0 + er) * 4 + c];
  }
  __syncthreads();

  // gather x = node_input[edge_dst] (L2-resident table)
  for (int idx = t; idx < 128 * 40; idx += 256) {
    int er = idx / 40, c = idx - er * 40;
    sX[er * 41 + c] = node_input[(long)sDst[er] * 40 + c];
  }

  // ---- GEMM1 (2 edges/thread): h = SILU_NORM * silu((d @ W1)/8) ----
  u64 accA[8], accB[8];
  #pragma unroll
  for (int j = 0; j < 8; j++) { accA[j] = 0ull; accB[j] = 0ull; }
  #pragma unroll 2
  for (int k = 0; k < 64; k++) {
    u64 d0 = dup2(sH[k * SHS + e]);
    u64 d1 = dup2(sH[k * SHS + e + 64]);
    const ulonglong2* wp = (const ulonglong2*)(sW + k * 64 + r * 16);
    ulonglong2 p0 = wp[0], p1 = wp[1], p2 = wp[2], p3 = wp[3];
    ffma2(accA[0], d0, p0.x);  ffma2(accA[1], d0, p0.y);
    ffma2(accA[2], d0, p1.x);  ffma2(accA[3], d0, p1.y);
    ffma2(accA[4], d0, p2.x);  ffma2(accA[5], d0, p2.y);
    ffma2(accA[6], d0, p3.x);  ffma2(accA[7], d0, p3.y);
    ffma2(accB[0], d1, p0.x);  ffma2(accB[1], d1, p0.y);
    ffma2(accB[2], d1, p1.x);  ffma2(accB[3], d1, p1.y);
    ffma2(accB[4], d1, p2.x);  ffma2(accB[5], d1, p2.y);
    ffma2(accB[6], d1, p3.x);  ffma2(accB[7], d1, p3.y);
  }
  __syncthreads();  // all reads of sH (dist) and sW (W1) complete

  #pragma unroll
  for (int j = 0; j < 8; j++) {
    float v0, v1;
    unpack2(accA[j], v0, v1);
    v0 *= 0.125f;  v1 *= 0.125f;
    sH[(r * 16 + 2 * j + 0) * SHS + e] = SILU_NORM * v0 / (1.0f + __expf(-v0));
    sH[(r * 16 + 2 * j + 1) * SHS + e] = SILU_NORM * v1 / (1.0f + __expf(-v1));
    unpack2(accB[j], v0, v1);
    v0 *= 0.125f;  v1 *= 0.125f;
    sH[(r * 16 + 2 * j + 0) * SHS + e + 64] = SILU_NORM * v0 / (1.0f + __expf(-v0));
    sH[(r * 16 + 2 * j + 1) * SHS + e + 64] = SILU_NORM * v1 / (1.0f + __expf(-v1));
  }

  // per-edge scalars
  float y0_[2], y1x_[2], y1y_[2], y1z_[2];
  #pragma unroll
  for (int ee = 0; ee < 2; ee++) {
    int eidx = e + 64 * ee;
    y0_[ee]  = sY[eidx * 5 + 0];
    y1x_[ee] = sY[eidx * 5 + 1];
    y1y_[ee] = sY[eidx * 5 + 2];
    y1z_[ee] = sY[eidx * 5 + 3];
  }

  float acc0[2][4] = {{0, 0, 0, 0}, {0, 0, 0, 0}};
  float a1[2][6]   = {{0, 0, 0, 0, 0, 0}, {0, 0, 0, 0, 0, 0}};

  // ---- GEMM2 + tensor product, 9 chunks of 64 permuted W2 columns ----
  do_chunk<0>(t, e, r, sm, y0_, y1x_, y1y_, y1z_, acc0, a1);
  do_chunk<1>(t, e, r, sm, y0_, y1x_, y1y_, y1z_, acc0, a1);
  do_chunk<2>(t, e, r, sm, y0_, y1x_, y1y_, y1z_, acc0, a1);
  do_chunk<3>(t, e, r, sm, y0_, y1x_, y1y_, y1z_, acc0, a1);
  do_chunk<4>(t, e, r, sm, y0_, y1x_, y1y_, y1z_, acc0, a1);
  do_chunk<5>(t, e, r, sm, y0_, y1x_, y1y_, y1z_, acc0, a1);
  do_chunk<6>(t, e, r, sm, y0_, y1x_, y1y_, y1z_, acc0, a1);
  do_chunk<7>(t, e, r, sm, y0_, y1x_, y1y_, y1z_, acc0, a1);
  do_chunk<8>(t, e, r, sm, y0_, y1x_, y1y_, y1z_, acc0, a1);

  // ---- scatter (disjoint columns across the 4 threads of an edge) ----
  #pragma unroll
  for (int ee = 0; ee < 2; ee++) {
    int base = sSrc[e + 64 * ee] * 40;
    #pragma unroll
    for (int gi = 0; gi < 4; gi++)
      atomicAdd(out + base + r + 4 * gi, S0F * acc0[ee][gi]);
    #pragma unroll
    for (int wp = 0; wp < 2; wp++)
      #pragma unroll
      for (int i = 0; i < 3; i++)
        atomicAdd(out + base + 16 + (2 * r + wp) * 3 + i, S0F * a1[ee][wp * 3 + i]);
  }
}

extern "C" void kernel_launch(void* const* d_in, const int* in_sizes, int n_in,
                              void* d_out, int out_size) {
  const float* node_input = (const float*)d_in[0];
  const int*   edge_src   = (const int*)d_in[1];
  const int*   edge_dst   = (const int*)d_in[2];
  const float* edge_attr  = (const float*)d_in[3];
  const float* dist       = (const float*)d_in[4];
  const float* W1         = (const float*)d_in[5];
  const float* W2         = (const float*)d_in[6];
  float* out = (float*)d_out;

  cudaFuncSetAttribute(fused_conv, cudaFuncAttributeMaxDynamicSharedMemorySize,
                       SMEM_BYTES);

  cudaMemsetAsync(out, 0, (size_t)out_size * sizeof(float));
  permute_w2<<<(WN + 127) / 128, 128>>>(W2);
  fused_conv<<<NBLK, 256, SMEM_BYTES>>>(node_input, edge_src, edge_dst,
                                        edge_attr, dist, W1, out);
}